// round 15
// baseline (speedup 1.0000x reference)
#include <cuda_runtime.h>
#include <cuda_bf16.h>
#include <cstdint>

// Problem constants (fixed by the reference)
#define NS 100000
#define NP 20000
#define NE 500000
#define FH 128
#define NP_PAD 20096   // NP rounded up to 128
#define NS_PAD 100096  // NS rounded up to 128

// ---------------- device scratch (static allocation only) ----------------
__device__ float g_xplay[NP * FH];
__device__ float g_p1   [NP * FH];
__device__ float g_s1   [NS * FH];

// bf16 hi/lo pre-split activations (padded to 128-row multiples; pad rows garbage, masked in epilogue)
__device__ __nv_bfloat16 g_aggPh[NP_PAD * FH], g_aggPl[NP_PAD * FH];
__device__ __nv_bfloat16 g_aggSh[NS_PAD * FH], g_aggSl[NS_PAD * FH];
__device__ __nv_bfloat16 g_sxh  [NS_PAD * FH], g_sxl  [NS_PAD * FH];
__device__ __nv_bfloat16 g_xph  [NP_PAD * FH], g_xpl  [NP_PAD * FH];
__device__ __nv_bfloat16 g_p1h  [NP_PAD * FH], g_p1l  [NP_PAD * FH];
__device__ __nv_bfloat16 g_s1h  [NS_PAD * FH], g_s1l  [NS_PAD * FH];

__device__ int g_cntP[NP], g_curP[NP];
__device__ int g_cntS[NS], g_curS[NS];
__device__ int g_rpP[NP + 1];
__device__ int g_rpS[NS + 1];
__device__ int g_csrP[NE];    // song ids grouped by playlist
__device__ int g_csrS[NE];    // playlist ids grouped by song
__device__ int g_partP[256];  // block partials for P scan
__device__ int g_partS[256];  // block partials for S scan

// pre-split weights: 8 mats, each [n=128][k=128], bf16 hi + lo
__device__ __nv_bfloat16 g_whi[8 * FH * FH];
__device__ __nv_bfloat16 g_wlo[8 * FH * FH];

// ---------------- helpers ----------------
__device__ __forceinline__ unsigned pack2bf(float f0, float f1) {
    // lower half = f0, upper half = f1
    unsigned r;
    asm("cvt.rn.bf16x2.f32 %0, %1, %2;" : "=r"(r) : "f"(f1), "f"(f0));
    return r;
}

// ---------------- CSR build ----------------
__global__ void zero_misc_kernel() {
    int i = blockIdx.x * blockDim.x + threadIdx.x;
    if (i < NS) { g_cntS[i] = 0; g_curS[i] = 0; }
    if (i < NP) { g_cntP[i] = 0; g_curP[i] = 0; }
}

__global__ void hist_kernel(const int* __restrict__ es, const int* __restrict__ ep) {
    int i = blockIdx.x * blockDim.x + threadIdx.x;
    if (i < NE) {
        atomicAdd(&g_cntS[es[i]], 1);
        atomicAdd(&g_cntP[ep[i]], 1);
    }
}

// ---- fused multi-block exclusive scans (P in blocks [0,nbP), S in [nbP,nbP+nbS)) ----
__global__ void scan1_both_kernel(int nbP) {
    __shared__ int s[512];
    int tid = threadIdx.x;
    bool isP = (blockIdx.x < (unsigned)nbP);
    int blk = isP ? blockIdx.x : (blockIdx.x - nbP);
    const int* cnt = isP ? g_cntP : g_cntS;
    int* rowptr    = isP ? g_rpP  : g_rpS;
    int* part      = isP ? g_partP : g_partS;
    int n          = isP ? NP : NS;
    int i = blk * 512 + tid;
    int v = (i < n) ? cnt[i] : 0;
    s[tid] = v;
    __syncthreads();
#pragma unroll
    for (int off = 1; off < 512; off <<= 1) {
        int a = (tid >= off) ? s[tid - off] : 0;
        __syncthreads();
        s[tid] += a;
        __syncthreads();
    }
    if (i < n) rowptr[i] = s[tid] - v;
    if (tid == 511) part[blk] = s[511];
}

__global__ void scan2_both_kernel(int nbP, int nbS) {
    __shared__ int s[256];
    int tid = threadIdx.x;
    int* part = (blockIdx.x == 0) ? g_partP : g_partS;
    int nb    = (blockIdx.x == 0) ? nbP : nbS;
    s[tid] = (tid < nb) ? part[tid] : 0;
    __syncthreads();
#pragma unroll
    for (int off = 1; off < 256; off <<= 1) {
        int a = (tid >= off) ? s[tid - off] : 0;
        __syncthreads();
        s[tid] += a;
        __syncthreads();
    }
    if (tid < nb) part[tid] = s[tid];
}

__global__ void scan3_both_kernel(int nbP, int nbS) {
    int tid = threadIdx.x;
    bool isP = (blockIdx.x < (unsigned)nbP);
    int blk = isP ? blockIdx.x : (blockIdx.x - nbP);
    int* rowptr = isP ? g_rpP : g_rpS;
    int* part   = isP ? g_partP : g_partS;
    int n       = isP ? NP : NS;
    int nb      = isP ? nbP : nbS;
    int i = blk * 512 + tid;
    if (i < n && blk > 0) rowptr[i] += part[blk - 1];
    if (i == 0) rowptr[n] = part[nb - 1];
}

__global__ void fill_kernel(const int* __restrict__ es, const int* __restrict__ ep) {
    int i = blockIdx.x * blockDim.x + threadIdx.x;
    if (i < NE) {
        int s = es[i], p = ep[i];
        int posP = atomicAdd(&g_curP[p], 1);
        g_csrP[g_rpP[p] + posP] = s;
        int posS = atomicAdd(&g_curS[s], 1);
        g_csrS[g_rpS[s] + posS] = p;
    }
}

// x_play = playlist_embed[playlist_node_id]; emit f32 + bf16 hi/lo
__global__ void gather_xplay_kernel(const float* __restrict__ pemb, const int* __restrict__ pid) {
    int i = blockIdx.x * blockDim.x + threadIdx.x;
    if (i < NP * 32) {
        int row = i >> 5;
        int q = i & 31;
        int src = pid[row];
        float4 v = *(const float4*)(pemb + (size_t)src * FH + q * 4);
        *(float4*)(g_xplay + (size_t)row * FH + q * 4) = v;
        unsigned h01 = pack2bf(v.x, v.y), h23 = pack2bf(v.z, v.w);
        float l0 = v.x - __uint_as_float(h01 << 16);
        float l1 = v.y - __uint_as_float(h01 & 0xffff0000u);
        float l2 = v.z - __uint_as_float(h23 << 16);
        float l3 = v.w - __uint_as_float(h23 & 0xffff0000u);
        size_t o = (size_t)row * FH + q * 4;
        *(uint2*)((unsigned short*)g_xph + o) = make_uint2(h01, h23);
        *(uint2*)((unsigned short*)g_xpl + o) = make_uint2(pack2bf(l0, l1), pack2bf(l2, l3));
    }
}

// song_x f32 -> bf16 hi/lo
__global__ void songx_split_kernel(const float* __restrict__ sx) {
    int i = blockIdx.x * blockDim.x + threadIdx.x;
    if (i < NS * 32) {
        int row = i >> 5;
        int q = i & 31;
        float4 v = *(const float4*)(sx + (size_t)row * FH + q * 4);
        unsigned h01 = pack2bf(v.x, v.y), h23 = pack2bf(v.z, v.w);
        float l0 = v.x - __uint_as_float(h01 << 16);
        float l1 = v.y - __uint_as_float(h01 & 0xffff0000u);
        float l2 = v.z - __uint_as_float(h23 << 16);
        float l3 = v.w - __uint_as_float(h23 & 0xffff0000u);
        size_t o = (size_t)row * FH + q * 4;
        *(uint2*)((unsigned short*)g_sxh + o) = make_uint2(h01, h23);
        *(uint2*)((unsigned short*)g_sxl + o) = make_uint2(pack2bf(l0, l1), pack2bf(l2, l3));
    }
}

// ---- fused weight pre-split: all 8 mats in one launch ----
struct WsplitArgs { const float* W[8]; };
__global__ void wsplit_all_kernel(WsplitArgs args) {
    int mat = blockIdx.x >> 6;                        // 64 blocks per matrix
    int i = (blockIdx.x & 63) * 256 + threadIdx.x;    // 0..16383
    int k = i >> 7, n = i & 127;
    float w = args.W[mat][k * FH + n];
    __nv_bfloat16 h = __float2bfloat16_rn(w);
    float hf = __bfloat162float(h);
    __nv_bfloat16 l = __float2bfloat16_rn(w - hf);
    g_whi[mat * FH * FH + n * FH + k] = h;            // [n][k]
    g_wlo[mat * FH * FH + n * FH + k] = l;
}

// ---------------- fused mean aggregation: writes bf16 hi/lo pairs ----------------
struct AggArgs {
    const float* srcP;   // messages into playlists
    const float* srcS;   // messages into songs
    __nv_bfloat16 *outPh, *outPl;
    __nv_bfloat16 *outSh, *outSl;
};
__global__ void agg_both_kernel(AggArgs a) {
    int warp = (blockIdx.x * blockDim.x + threadIdx.x) >> 5;
    int lane = threadIdx.x & 31;
    const float* src;
    const int* rowptr;
    const int* cols;
    __nv_bfloat16 *outh, *outl;
    int row;
    if (warp < NP) {
        src = a.srcP; rowptr = g_rpP; cols = g_csrP; outh = a.outPh; outl = a.outPl; row = warp;
    } else if (warp < NP + NS) {
        src = a.srcS; rowptr = g_rpS; cols = g_csrS; outh = a.outSh; outl = a.outSl; row = warp - NP;
    } else return;
    int beg = rowptr[row], end = rowptr[row + 1];
    float4 acc = make_float4(0.f, 0.f, 0.f, 0.f);
    int e = beg;
    for (; e + 3 < end; e += 4) {
        int c0 = cols[e], c1 = cols[e + 1], c2 = cols[e + 2], c3 = cols[e + 3];
        float4 v0 = *(const float4*)(src + (size_t)c0 * FH + lane * 4);
        float4 v1 = *(const float4*)(src + (size_t)c1 * FH + lane * 4);
        float4 v2 = *(const float4*)(src + (size_t)c2 * FH + lane * 4);
        float4 v3 = *(const float4*)(src + (size_t)c3 * FH + lane * 4);
        acc.x += (v0.x + v1.x) + (v2.x + v3.x);
        acc.y += (v0.y + v1.y) + (v2.y + v3.y);
        acc.z += (v0.z + v1.z) + (v2.z + v3.z);
        acc.w += (v0.w + v1.w) + (v2.w + v3.w);
    }
    for (; e < end; ++e) {
        int c0 = cols[e];
        float4 v0 = *(const float4*)(src + (size_t)c0 * FH + lane * 4);
        acc.x += v0.x; acc.y += v0.y; acc.z += v0.z; acc.w += v0.w;
    }
    int d = end - beg;
    float inv = 1.f / (float)(d > 0 ? d : 1);
    acc.x *= inv; acc.y *= inv; acc.z *= inv; acc.w *= inv;
    unsigned h01 = pack2bf(acc.x, acc.y), h23 = pack2bf(acc.z, acc.w);
    float l0 = acc.x - __uint_as_float(h01 << 16);
    float l1 = acc.y - __uint_as_float(h01 & 0xffff0000u);
    float l2 = acc.z - __uint_as_float(h23 << 16);
    float l3 = acc.w - __uint_as_float(h23 & 0xffff0000u);
    size_t o = (size_t)row * FH + lane * 4;
    *(uint2*)((unsigned short*)outh + o) = make_uint2(h01, h23);
    *(uint2*)((unsigned short*)outl + o) = make_uint2(pack2bf(l0, l1), pack2bf(l2, l3));
}

// ---------------- fused 3xBF16 GEMM pair (ldmatrix + register double-buffer) ------
// Each sub-problem: out[M,128] = A0@W0 + A1@W1 + b (opt relu); A pre-split bf16 hi/lo.

#define MMA_BF16(acc, a, b0, b1)                                                   \
    asm volatile("mma.sync.aligned.m16n8k16.row.col.f32.bf16.bf16.f32 "            \
                 "{%0,%1,%2,%3},{%4,%5,%6,%7},{%8,%9},{%0,%1,%2,%3};"              \
                 : "+f"(acc[0]), "+f"(acc[1]), "+f"(acc[2]), "+f"(acc[3])          \
                 : "r"(a[0]), "r"(a[1]), "r"(a[2]), "r"(a[3]), "r"(b0), "r"(b1))

#define LDSM4(r0, r1, r2, r3, addr)                                                \
    asm volatile("ldmatrix.sync.aligned.m8n8.x4.shared.b16 {%0,%1,%2,%3},[%4];"    \
                 : "=r"(r0), "=r"(r1), "=r"(r2), "=r"(r3) : "r"(addr))

#define ALD 40   // bf16 elements per smem row (32 data + 8 pad) -> conflict-free

struct GemmSub {
    const __nv_bfloat16 *A0h, *A0l, *A1h, *A1l;       // [M_pad][128]
    const __nv_bfloat16 *Wh0, *Wl0, *Wh1, *Wl1;       // [128][128]
    const float* bias;
    float* out;
    __nv_bfloat16 *outH, *outL;                       // optional pair emit (or null)
    int M;
    int relu;
};
struct GemmPairArgs { GemmSub s[2]; int gridA; };

__device__ __forceinline__ void gemm_load_tile(const GemmSub& P, int kc, int tid,
                                               int blockRow, int4* r) {
    int seg = kc >> 2, kcc = kc & 3;
    const __nv_bfloat16* ah = seg ? P.A1h : P.A0h;
    const __nv_bfloat16* al = seg ? P.A1l : P.A0l;
    const __nv_bfloat16* bh = seg ? P.Wh1 : P.Wh0;
    const __nv_bfloat16* bl = seg ? P.Wl1 : P.Wl0;
#pragma unroll
    for (int j = 0; j < 2; ++j) {
        int slot = j * 256 + tid;
        int row = slot >> 2, kq = slot & 3;
        size_t ga = (size_t)(blockRow + row) * FH + kcc * 32 + kq * 8;
        size_t gb = (size_t)row * FH + kcc * 32 + kq * 8;
        r[0 + j] = *(const int4*)((const unsigned short*)ah + ga);
        r[2 + j] = *(const int4*)((const unsigned short*)al + ga);
        r[4 + j] = *(const int4*)((const unsigned short*)bh + gb);
        r[6 + j] = *(const int4*)((const unsigned short*)bl + gb);
    }
}

__global__ __launch_bounds__(256)
void gemm_pair_kernel(GemmPairArgs args) {
    __shared__ unsigned short Ah[128 * ALD], Al[128 * ALD];
    __shared__ unsigned short Bh[128 * ALD], Bl[128 * ALD];
    __shared__ float bias_s[128];

    int which = (blockIdx.x < (unsigned)args.gridA) ? 0 : 1;
    const GemmSub& P = args.s[which];
    int blockRow = (which ? (blockIdx.x - args.gridA) : blockIdx.x) * 128;
    int M = P.M;

    int tid = threadIdx.x;
    int lane = tid & 31;
    int wid = tid >> 5;
    int warp_m = wid & 3;    // 4 warps along M (32 rows each)
    int warp_n = wid >> 2;   // 2 warps along N (64 cols each)
    int g = lane >> 2;
    int r = lane & 3;

    if (tid < 128) bias_s[tid] = P.bias[tid];

    // ldmatrix smem byte offsets (per lane)
    unsigned baseAh = (unsigned)__cvta_generic_to_shared(Ah);
    unsigned baseAl = (unsigned)__cvta_generic_to_shared(Al);
    unsigned baseBh = (unsigned)__cvta_generic_to_shared(Bh);
    unsigned baseBl = (unsigned)__cvta_generic_to_shared(Bl);
    int la = lane & 15, ha = lane >> 4;
    unsigned offA[2];
#pragma unroll
    for (int mt = 0; mt < 2; ++mt)
        offA[mt] = ((warp_m * 32 + mt * 16 + la) * ALD + ha * 8) * 2;
    unsigned offB[4];
#pragma unroll
    for (int p = 0; p < 4; ++p)
        offB[p] = ((warp_n * 64 + p * 16 + ((lane >> 4) & 1) * 8 + (lane & 7)) * ALD
                   + ((lane >> 3) & 1) * 8) * 2;

    float acc[2][8][4];
#pragma unroll
    for (int mt = 0; mt < 2; ++mt)
#pragma unroll
        for (int nt = 0; nt < 8; ++nt)
#pragma unroll
            for (int j = 0; j < 4; ++j) acc[mt][nt][j] = 0.f;

    int4 cur[8], nxt[8];
    gemm_load_tile(P, 0, tid, blockRow, cur);

#pragma unroll
    for (int kc = 0; kc < 8; ++kc) {
        // store current tile to smem
#pragma unroll
        for (int j = 0; j < 2; ++j) {
            int slot = j * 256 + tid;
            int row = slot >> 2, kq = slot & 3;
            unsigned off = row * ALD + kq * 8;
            *(int4*)&Ah[off] = cur[0 + j];
            *(int4*)&Al[off] = cur[2 + j];
            *(int4*)&Bh[off] = cur[4 + j];
            *(int4*)&Bl[off] = cur[6 + j];
        }
        __syncthreads();
        if (kc < 7) gemm_load_tile(P, kc + 1, tid, blockRow, nxt);

        // compute: 2 x k16 steps
#pragma unroll
        for (int k16 = 0; k16 < 2; ++k16) {
            unsigned kb = k16 * 32;   // 16 bf16 * 2B
            unsigned ahi[2][4], alo[2][4];
#pragma unroll
            for (int mt = 0; mt < 2; ++mt) {
                LDSM4(ahi[mt][0], ahi[mt][1], ahi[mt][2], ahi[mt][3], baseAh + offA[mt] + kb);
                LDSM4(alo[mt][0], alo[mt][1], alo[mt][2], alo[mt][3], baseAl + offA[mt] + kb);
            }
#pragma unroll
            for (int p = 0; p < 4; ++p) {
                unsigned bh[4], bl[4];
                LDSM4(bh[0], bh[1], bh[2], bh[3], baseBh + offB[p] + kb);
                LDSM4(bl[0], bl[1], bl[2], bl[3], baseBl + offB[p] + kb);
#pragma unroll
                for (int mt = 0; mt < 2; ++mt) {
                    MMA_BF16(acc[mt][2 * p],     ahi[mt], bh[0], bh[1]);  // hi*hi
                    MMA_BF16(acc[mt][2 * p],     ahi[mt], bl[0], bl[1]);  // hi*lo
                    MMA_BF16(acc[mt][2 * p],     alo[mt], bh[0], bh[1]);  // lo*hi
                    MMA_BF16(acc[mt][2 * p + 1], ahi[mt], bh[2], bh[3]);
                    MMA_BF16(acc[mt][2 * p + 1], ahi[mt], bl[2], bl[3]);
                    MMA_BF16(acc[mt][2 * p + 1], alo[mt], bh[2], bh[3]);
                }
            }
        }
        __syncthreads();
#pragma unroll
        for (int j = 0; j < 8; ++j) cur[j] = nxt[j];
    }

    // epilogue
    bool emit_pair = (P.outH != nullptr);
#pragma unroll
    for (int mt = 0; mt < 2; ++mt) {
#pragma unroll
        for (int nt = 0; nt < 8; ++nt) {
            int col = warp_n * 64 + nt * 8 + r * 2;
            float bv0 = bias_s[col], bv1 = bias_s[col + 1];
            int row0 = blockRow + warp_m * 32 + mt * 16 + g;
            int row1 = row0 + 8;
            float v0 = acc[mt][nt][0] + bv0;
            float v1 = acc[mt][nt][1] + bv1;
            float v2 = acc[mt][nt][2] + bv0;
            float v3 = acc[mt][nt][3] + bv1;
            if (P.relu) {
                v0 = fmaxf(v0, 0.f); v1 = fmaxf(v1, 0.f);
                v2 = fmaxf(v2, 0.f); v3 = fmaxf(v3, 0.f);
            }
            if (row0 < M) {
                *(float2*)(P.out + (size_t)row0 * 128 + col) = make_float2(v0, v1);
                if (emit_pair) {
                    unsigned h = pack2bf(v0, v1);
                    float l0 = v0 - __uint_as_float(h << 16);
                    float l1 = v1 - __uint_as_float(h & 0xffff0000u);
                    *(unsigned*)((unsigned short*)P.outH + (size_t)row0 * 128 + col) = h;
                    *(unsigned*)((unsigned short*)P.outL + (size_t)row0 * 128 + col) = pack2bf(l0, l1);
                }
            }
            if (row1 < M) {
                *(float2*)(P.out + (size_t)row1 * 128 + col) = make_float2(v2, v3);
                if (emit_pair) {
                    unsigned h = pack2bf(v2, v3);
                    float l2 = v2 - __uint_as_float(h << 16);
                    float l3 = v3 - __uint_as_float(h & 0xffff0000u);
                    *(unsigned*)((unsigned short*)P.outH + (size_t)row1 * 128 + col) = h;
                    *(unsigned*)((unsigned short*)P.outL + (size_t)row1 * 128 + col) = pack2bf(l2, l3);
                }
            }
        }
    }
}

// ---------------- host launcher ----------------
static float* sym_f(const void* s) { void* p = nullptr; cudaGetSymbolAddress(&p, s); return (float*)p; }
static __nv_bfloat16* sym_b(const void* s) { void* p = nullptr; cudaGetSymbolAddress(&p, s); return (__nv_bfloat16*)p; }

extern "C" void kernel_launch(void* const* d_in, const int* in_sizes, int n_in,
                              void* d_out, int out_size) {
    const float* song_x  = (const float*)d_in[0];
    const int*   pid     = (const int*)d_in[1];
    const int*   e_song  = (const int*)d_in[2];
    const int*   e_play  = (const int*)d_in[3];
    const float* pemb    = (const float*)d_in[4];
    const float* b1_sp = (const float*)d_in[7];
    const float* b1_ps = (const float*)d_in[10];
    const float* b2_sp = (const float*)d_in[13];
    const float* b2_ps = (const float*)d_in[16];

    float* out = (float*)d_out;
    float* out_s2 = out;                      // [NS,128] first
    float* out_p2 = out + (size_t)NS * FH;    // [NP,128] second

    float* xplay = sym_f(g_xplay);
    float* p1    = sym_f(g_p1);
    float* s1    = sym_f(g_s1);
    __nv_bfloat16* whi = sym_b(g_whi);
    __nv_bfloat16* wlo = sym_b(g_wlo);
    __nv_bfloat16* aggPh = sym_b(g_aggPh); __nv_bfloat16* aggPl = sym_b(g_aggPl);
    __nv_bfloat16* aggSh = sym_b(g_aggSh); __nv_bfloat16* aggSl = sym_b(g_aggSl);
    __nv_bfloat16* sxh = sym_b(g_sxh); __nv_bfloat16* sxl = sym_b(g_sxl);
    __nv_bfloat16* xph = sym_b(g_xph); __nv_bfloat16* xpl = sym_b(g_xpl);
    __nv_bfloat16* p1h = sym_b(g_p1h); __nv_bfloat16* p1l = sym_b(g_p1l);
    __nv_bfloat16* s1h = sym_b(g_s1h); __nv_bfloat16* s1l = sym_b(g_s1l);

    // ---- weight pre-split: single launch for all 8 matrices ----
    WsplitArgs wa;
    wa.W[0] = (const float*)d_in[5];   // Wl1_sp
    wa.W[1] = (const float*)d_in[6];   // Wr1_sp
    wa.W[2] = (const float*)d_in[8];   // Wl1_ps
    wa.W[3] = (const float*)d_in[9];   // Wr1_ps
    wa.W[4] = (const float*)d_in[11];  // Wl2_sp
    wa.W[5] = (const float*)d_in[12];  // Wr2_sp
    wa.W[6] = (const float*)d_in[14];  // Wl2_ps
    wa.W[7] = (const float*)d_in[15];  // Wr2_ps
    wsplit_all_kernel<<<512, 256>>>(wa);
    songx_split_kernel<<<(NS * 32 + 255) / 256, 256>>>(song_x);

    // ---- CSR build ----
    zero_misc_kernel<<<(NS + 255) / 256, 256>>>();
    hist_kernel<<<(NE + 255) / 256, 256>>>(e_song, e_play);

    int nbP = (NP + 511) / 512;   // 40
    int nbS = (NS + 511) / 512;   // 196
    scan1_both_kernel<<<nbP + nbS, 512>>>(nbP);
    scan2_both_kernel<<<2, 256>>>(nbP, nbS);
    scan3_both_kernel<<<nbP + nbS, 512>>>(nbP, nbS);

    fill_kernel<<<(NE + 255) / 256, 256>>>(e_song, e_play);
    gather_xplay_kernel<<<(NP * 32 + 255) / 256, 256>>>(pemb, pid);

    const int AGG_WPB = 8;
    const int AGG_GRID = (NP + NS + AGG_WPB - 1) / AGG_WPB;
    int gridA = (NP + 127) / 128;   // 157
    int gridB = (NS + 127) / 128;   // 782

#define WH(i) (whi + (i) * FH * FH)
#define WL(i) (wlo + (i) * FH * FH)
    // ---- conv1 ----
    {
        AggArgs a{song_x, xplay, aggPh, aggPl, aggSh, aggSl};
        agg_both_kernel<<<AGG_GRID, AGG_WPB * 32>>>(a);
        GemmPairArgs ga;
        ga.s[0] = {aggPh, aggPl, xph, xpl, WH(0), WL(0), WH(1), WL(1), b1_sp, p1, p1h, p1l, NP, 1};
        ga.s[1] = {aggSh, aggSl, sxh, sxl, WH(2), WL(2), WH(3), WL(3), b1_ps, s1, s1h, s1l, NS, 1};
        ga.gridA = gridA;
        gemm_pair_kernel<<<gridA + gridB, 256>>>(ga);
    }
    // ---- conv2 ----
    {
        AggArgs a{s1, p1, aggPh, aggPl, aggSh, aggSl};
        agg_both_kernel<<<AGG_GRID, AGG_WPB * 32>>>(a);
        GemmPairArgs ga;
        ga.s[0] = {aggPh, aggPl, p1h, p1l, WH(4), WL(4), WH(5), WL(5), b2_sp, out_p2, nullptr, nullptr, NP, 0};
        ga.s[1] = {aggSh, aggSl, s1h, s1l, WH(6), WL(6), WH(7), WL(7), b2_ps, out_s2, nullptr, nullptr, NS, 0};
        ga.gridA = gridA;
        gemm_pair_kernel<<<gridA + gridB, 256>>>(ga);
    }
#undef WH
#undef WL

    (void)in_sizes; (void)n_in; (void)out_size;
}